// round 11
// baseline (speedup 1.0000x reference)
#include <cuda_runtime.h>
#include <cuda_bf16.h>

#define NUM_BINS    15
#define NUM_CLASSES 19
#define HW          (512 * 512)
#define BATCH       8

// Two pixels per thread (float2 per class). Grid: x = HW/2/256 blocks, y = batch.
// launch_bounds(256,4) caps regs at 64 -> 4 blocks = 32 warps/SM, with 2x the
// bytes-in-flight per warp vs the scalar version and half the instructions/byte.
// Warp loads 32 consecutive float2 = one 256B (2-line) request, fully coalesced.
__global__ __launch_bounds__(256, 4)
void calib_kernel(const float* __restrict__ logits,
                  const float* __restrict__ val_freqs,
                  float* __restrict__ out)
{
    __shared__ float sfreq[NUM_CLASSES * NUM_BINS];  // 285 floats
    for (int i = threadIdx.x; i < NUM_CLASSES * NUM_BINS; i += blockDim.x)
        sfreq[i] = val_freqs[i];
    __syncthreads();

    const int s2 = blockIdx.x * blockDim.x + threadIdx.x;  // float2 index in image
    const int b  = blockIdx.y;

    const float2* __restrict__ in2  =
        (const float2*)(logits + (long long)b * (NUM_CLASSES * HW)) + s2;
    float2* __restrict__ out2 =
        (float2*)(out + (long long)b * (NUM_CLASSES * HW)) + s2;
    const int cstride2 = HW / 2;   // class stride in float2 units

    // ---- load all 19 classes (front-batched, high MLP, streaming) ----
    float2 v[NUM_CLASSES];
    #pragma unroll
    for (int c = 0; c < NUM_CLASSES; c++)
        v[c] = __ldcs(in2 + c * cstride2);

    // ---- per-lane max over classes ----
    float mxx = v[0].x, mxy = v[0].y;
    #pragma unroll
    for (int c = 1; c < NUM_CLASSES; c++) {
        mxx = fmaxf(mxx, v[c].x);
        mxy = fmaxf(mxy, v[c].y);
    }

    // ---- exp(x - max), sum ----
    float sx = 0.f, sy = 0.f;
    #pragma unroll
    for (int c = 0; c < NUM_CLASSES; c++) {
        v[c].x = expf(v[c].x - mxx);  sx += v[c].x;
        v[c].y = expf(v[c].y - mxy);  sy += v[c].y;
    }
    const float scx = (float)NUM_BINS / sx;   // bin = floor(e_c * 15 / sum)
    const float scy = (float)NUM_BINS / sy;

    // ---- bin + table gather + class-sum (cal overwrites v in place) ----
    float cx = 0.f, cy = 0.f;
    #pragma unroll
    for (int c = 0; c < NUM_CLASSES; c++) {
        const float* f = sfreq + c * NUM_BINS;
        int bx = min((int)(v[c].x * scx), NUM_BINS - 1);
        int by = min((int)(v[c].y * scy), NUM_BINS - 1);
        v[c].x = f[bx];  cx += v[c].x;
        v[c].y = f[by];  cy += v[c].y;
    }

    // ---- normalize (guard s==0 -> 1, matching reference) ----
    cx = (cx == 0.f) ? 1.f : cx;
    cy = (cy == 0.f) ? 1.f : cy;
    const float ix = 1.0f / cx;
    const float iy = 1.0f / cy;

    // ---- store (streaming) ----
    #pragma unroll
    for (int c = 0; c < NUM_CLASSES; c++) {
        float2 o;
        o.x = v[c].x * ix;
        o.y = v[c].y * iy;
        __stcs(out2 + c * cstride2, o);
    }
}

extern "C" void kernel_launch(void* const* d_in, const int* in_sizes, int n_in,
                              void* d_out, int out_size)
{
    const float* logits    = (const float*)d_in[0];  // [8,19,512,512] f32
    const float* val_freqs = (const float*)d_in[1];  // [19,15] f32
    float* out = (float*)d_out;

    dim3 grid((HW / 2) / 256, BATCH);   // (512, 8)
    calib_kernel<<<grid, 256>>>(logits, val_freqs, out);
}